// round 2
// baseline (speedup 1.0000x reference)
#include <cuda_runtime.h>

#define T_LEN   1024
#define N_ORD   64
#define M_ROWS  512            // 4*2*64
#define KCHUNK  64
#define KSPLIT  (T_LEN / KCHUNK)   // 16
#define MTILE   64
#define MTILES  (M_ROWS / MTILE)   // 8
#define SSTR    65             // padded smem row stride (conflict-free column reads)

__global__ void hippo_zero(float* __restrict__ out) {
    int i = blockIdx.x * blockDim.x + threadIdx.x;
    ((float4*)out)[i] = make_float4(0.f, 0.f, 0.f, 0.f);
}

// out[r, n] = sum_t u[r, t] * K[n, T-1-t]
// Split-K GEMM: grid = (MTILES, KSPLIT), block = 256 threads.
// Block tile: 64 rows x 64 cols over a K-chunk of 64; per-thread 4x4 register tile.
__global__ __launch_bounds__(256, 1) void hippo_gemm(
    const float* __restrict__ u,
    const float* __restrict__ Km,
    float* __restrict__ out)
{
    __shared__ float uS[MTILE * SSTR];   // uS[r][kk]
    __shared__ float kS[N_ORD * SSTR];   // kS[n][kk] = Km[n][T-1-(k0+kk)]

    const int m0  = blockIdx.x * MTILE;
    const int k0  = blockIdx.y * KCHUNK;
    const int tid = threadIdx.x;

    // ---- load u tile (64 rows x 64 t), float4 coalesced ----
    #pragma unroll
    for (int i = tid; i < MTILE * KCHUNK / 4; i += 256) {
        int r  = i >> 4;             // row within tile
        int c4 = (i & 15) << 2;      // kk base
        float4 v = *(const float4*)(u + (m0 + r) * T_LEN + k0 + c4);
        uS[r * SSTR + c4 + 0] = v.x;
        uS[r * SSTR + c4 + 1] = v.y;
        uS[r * SSTR + c4 + 2] = v.z;
        uS[r * SSTR + c4 + 3] = v.w;
    }
    // ---- load K tile, time-reversed during store ----
    #pragma unroll
    for (int i = tid; i < N_ORD * KCHUNK / 4; i += 256) {
        int n  = i >> 4;
        int c4 = (i & 15) << 2;
        // kS[n][c4+q] = Km[n][T-1-k0-c4-q]; read the aligned float4 covering those 4.
        float4 g = *(const float4*)(Km + n * T_LEN + (T_LEN - 4 - k0 - c4));
        kS[n * SSTR + c4 + 0] = g.w;
        kS[n * SSTR + c4 + 1] = g.z;
        kS[n * SSTR + c4 + 2] = g.y;
        kS[n * SSTR + c4 + 3] = g.x;
    }
    __syncthreads();

    const int tx = tid & 15;   // cols tx*4 .. tx*4+3
    const int ty = tid >> 4;   // rows ty*4 .. ty*4+3

    float acc[4][4] = {};

    #pragma unroll 16
    for (int kk = 0; kk < KCHUNK; kk++) {
        float a[4], b[4];
        #pragma unroll
        for (int i = 0; i < 4; i++) a[i] = uS[(ty * 4 + i) * SSTR + kk];
        #pragma unroll
        for (int j = 0; j < 4; j++) b[j] = kS[(tx * 4 + j) * SSTR + kk];
        #pragma unroll
        for (int i = 0; i < 4; i++)
            #pragma unroll
            for (int j = 0; j < 4; j++)
                acc[i][j] = fmaf(a[i], b[j], acc[i][j]);
    }

    // ---- accumulate split-K partials ----
    #pragma unroll
    for (int i = 0; i < 4; i++)
        #pragma unroll
        for (int j = 0; j < 4; j++)
            atomicAdd(out + (m0 + ty * 4 + i) * N_ORD + tx * 4 + j, acc[i][j]);
}

extern "C" void kernel_launch(void* const* d_in, const int* in_sizes, int n_in,
                              void* d_out, int out_size)
{
    const float* u  = (const float*)d_in[0];   // (4,2,64,1024) = 512 x 1024
    const float* Km = (const float*)d_in[1];   // (64,1024)
    // Defensive: swap if metadata ordered K first (sizes are distinct).
    if (n_in >= 2 && in_sizes[0] == N_ORD * T_LEN && in_sizes[1] == M_ROWS * T_LEN) {
        u  = (const float*)d_in[1];
        Km = (const float*)d_in[0];
    }
    float* out = (float*)d_out;                // (4,2,64,64) = 32768 floats

    hippo_zero<<<(M_ROWS * N_ORD / 4) / 256, 256>>>(out);   // 32 blocks
    dim3 grid(MTILES, KSPLIT);                               // 8 x 16 = 128 blocks
    hippo_gemm<<<grid, 256>>>(u, Km, out);
}